// round 7
// baseline (speedup 1.0000x reference)
#include <cuda_runtime.h>
#include <stdint.h>
#include <math.h>

#define N_NODES 50000
#define N_EDGES 200000

typedef unsigned long long ull;

// ---------------- scratch (static __device__; no allocation allowed) ----------------
__device__ __align__(16) float g_h1 [(size_t)N_EDGES * 256];    // enn hidden 1
__device__ __align__(16) float g_big1[(size_t)N_EDGES * 1024];  // enn hidden 2
__device__ __align__(16) float g_big2[(size_t)N_EDGES * 1024];  // z = elu(h2@w3+b3)
__device__ __align__(16) float g_agg [N_NODES * 64];
__device__ __align__(16) float g_xcur[N_NODES * 64];
__device__ __align__(16) float g_xin [N_NODES * 64];
__device__ __align__(16) float g_hbuf[N_NODES * 64];
__device__ __align__(16) float g_gh1 [N_NODES * 256];
__device__ __align__(16) float g_gh2 [N_NODES * 256];

__device__ __forceinline__ float* sbuf(int id) {
    switch (id) {
        case 1: return g_h1;
        case 2: return g_big1;
        case 3: return g_big2;
        case 4: return g_agg;
        case 5: return g_xcur;
        case 6: return g_xin;
        case 7: return g_hbuf;
        case 8: return g_gh1;
        case 9: return g_gh2;
    }
    return nullptr;
}

__device__ __forceinline__ float elu_f(float v) {
    return v > 0.f ? v : expm1f(v);
}

__device__ __forceinline__ ull dup_f(float f) {
    uint32_t u = __float_as_uint(f);
    return ((ull)u << 32) | u;
}

// ============ packed-f32x2 GEMM: C = elu(A@B + bias) (exact fp32) ============
// A: [M,K] row-major (Aid=0 -> Aext else scratch); B: [K,N] row-major weights.
// CTA tile 128x128, BK=16, 256 threads, per-thread 8(M)x8(N).
// f32x2 lanes paired along M (free from As layout); B duplicated {b,b} in SMEM.
__global__ __launch_bounds__(256, 2)
void gemm2_k(int M, int N, int K,
             const float* __restrict__ Aext, int Aid,
             const float* __restrict__ B,
             const float* __restrict__ bias, int Cid)
{
    const float* A = (Aid == 0) ? Aext : sbuf(Aid);
    float*       C = sbuf(Cid);

    __shared__ __align__(16) ull AsU[16 * 64];    // [k][m/2]  (8 KB)
    __shared__ __align__(16) ull Bs2[16 * 128];   // [k][n] dup pairs (16 KB)
    __shared__ float sbias[128];
    float* Asf = (float*)AsU;

    const int tid = threadIdx.x;
    const int tx = tid & 15;        // 16 threads along N
    const int ty = tid >> 4;        // 16 threads along M
    const int m0 = blockIdx.y * 128;
    const int n0 = blockIdx.x * 128;

    if (tid < 128) sbias[tid] = bias[n0 + tid];

    ull acc2[4][8];
#pragma unroll
    for (int p = 0; p < 4; p++)
#pragma unroll
        for (int j = 0; j < 8; j++) acc2[p][j] = 0ull;

    for (int kk = 0; kk < K; kk += 16) {
        __syncthreads();
        // ---- A tile [128 x 16] -> As[k][m] (transposed scalar stores) ----
#pragma unroll
        for (int it = 0; it < 2; ++it) {
            int i = tid * 4 + it * 1024;
            int r = i >> 4;            // m-row 0..127
            int c = i & 15;            // k 0..12 step4
            int m = m0 + r;
            float4 v = make_float4(0.f, 0.f, 0.f, 0.f);
            if (m < M) v = *(const float4*)(A + (size_t)m * K + kk + c);
            Asf[(c + 0) * 128 + r] = v.x;
            Asf[(c + 1) * 128 + r] = v.y;
            Asf[(c + 2) * 128 + r] = v.z;
            Asf[(c + 3) * 128 + r] = v.w;
        }
        // ---- B tile [16 x 128] -> Bs2[k][n] duplicated pairs ----
#pragma unroll
        for (int it = 0; it < 2; ++it) {
            int i = tid * 4 + it * 1024;
            int r = i >> 7;            // k 0..15
            int c = i & 127;           // n
            float4 v = *(const float4*)(B + (size_t)(kk + r) * N + n0 + c);
            ulonglong2 w0 = { dup_f(v.x), dup_f(v.y) };
            ulonglong2 w1 = { dup_f(v.z), dup_f(v.w) };
            *(ulonglong2*)(Bs2 + r * 128 + c)     = w0;
            *(ulonglong2*)(Bs2 + r * 128 + c + 2) = w1;
        }
        __syncthreads();

#pragma unroll
        for (int k = 0; k < 16; ++k) {
            ulonglong2 A0 = *(const ulonglong2*)(AsU + k * 64 + ty * 4);
            ulonglong2 A1 = *(const ulonglong2*)(AsU + k * 64 + ty * 4 + 2);
            ull a2[4] = { A0.x, A0.y, A1.x, A1.y };
            ull bb[8];
#pragma unroll
            for (int q = 0; q < 4; ++q) {
                ulonglong2 t = *(const ulonglong2*)(Bs2 + k * 128 + tx * 8 + q * 2);
                bb[q * 2] = t.x; bb[q * 2 + 1] = t.y;
            }
#pragma unroll
            for (int p = 0; p < 4; ++p)
#pragma unroll
                for (int j = 0; j < 8; ++j)
                    asm("fma.rn.f32x2 %0, %1, %2, %0;"
                        : "+l"(acc2[p][j]) : "l"(a2[p]), "l"(bb[j]));
        }
    }

    // ---- epilogue: unpack pairs, bias + ELU, float4 stores ----
#pragma unroll
    for (int p = 0; p < 4; ++p) {
        int r0 = m0 + ty * 8 + 2 * p;
        int r1 = r0 + 1;
        float lo[8], hi[8];
#pragma unroll
        for (int j = 0; j < 8; ++j) {
            ull v = acc2[p][j];
            float b = sbias[tx * 8 + j];
            lo[j] = elu_f(__uint_as_float((uint32_t)v) + b);
            hi[j] = elu_f(__uint_as_float((uint32_t)(v >> 32)) + b);
        }
        if (r0 < M) {
            float* dst = C + (size_t)r0 * N + n0 + tx * 8;
            *(float4*)dst       = make_float4(lo[0], lo[1], lo[2], lo[3]);
            *(float4*)(dst + 4) = make_float4(lo[4], lo[5], lo[6], lo[7]);
        }
        if (r1 < M) {
            float* dst = C + (size_t)r1 * N + n0 + tx * 8;
            *(float4*)dst       = make_float4(hi[0], hi[1], hi[2], hi[3]);
            *(float4*)(dst + 4) = make_float4(hi[4], hi[5], hi[6], hi[7]);
        }
    }
}

// ---------------- SIMT tiled GEMM (exact fp32) for small-N layers -----------------
template<int BM, int BN, int BK, int TM, int TN, bool ELU_ACT, bool ADDD, bool STORE4>
__global__ __launch_bounds__(256, 2)
void gemm_k(int M, int N, int K,
            const float* __restrict__ Aext, int Aid,
            const float* __restrict__ B,
            const float* __restrict__ bias,
            int Did, int Cid,
            float* __restrict__ out4, int layer)
{
    const float* A = (Aid == 0) ? Aext : sbuf(Aid);
    const float* D = ADDD ? sbuf(Did) : nullptr;
    float*       C = sbuf(Cid);

    __shared__ float As[BK][BM];
    __shared__ float Bs[BK][BN];

    const int tid = threadIdx.x;
    constexpr int TW = BN / TN;
    const int tx = tid % TW;
    const int ty = tid / TW;
    const int m0 = blockIdx.y * BM;
    const int n0 = blockIdx.x * BN;

    float acc[TM][TN];
#pragma unroll
    for (int i = 0; i < TM; i++)
#pragma unroll
        for (int j = 0; j < TN; j++) acc[i][j] = 0.f;

    constexpr int A_ITERS = (BM * BK) / (256 * 4);
    constexpr int B_ITERS = (BK * BN) / (256 * 4);

    for (int kk = 0; kk < K; kk += BK) {
#pragma unroll
        for (int it = 0; it < A_ITERS; ++it) {
            int i = tid * 4 + it * 1024;
            int r = i / BK;
            int c = i % BK;
            int m = m0 + r;
            float4 v;
            if (m < M) v = *(const float4*)(A + (size_t)m * K + kk + c);
            else       v = make_float4(0.f, 0.f, 0.f, 0.f);
            As[c + 0][r] = v.x;
            As[c + 1][r] = v.y;
            As[c + 2][r] = v.z;
            As[c + 3][r] = v.w;
        }
#pragma unroll
        for (int it = 0; it < B_ITERS; ++it) {
            int i = tid * 4 + it * 1024;
            int r = i / BN;
            int c = i % BN;
            *(float4*)(&Bs[r][c]) = *(const float4*)(B + (size_t)(kk + r) * N + n0 + c);
        }
        __syncthreads();

#pragma unroll
        for (int k = 0; k < BK; k++) {
            float a[TM], b[TN];
#pragma unroll
            for (int i = 0; i < TM; i += 4)
                *(float4*)&a[i] = *(const float4*)&As[k][ty * TM + i];
#pragma unroll
            for (int j = 0; j < TN; j += 4)
                *(float4*)&b[j] = *(const float4*)&Bs[k][tx * TN + j];
#pragma unroll
            for (int i = 0; i < TM; i++)
#pragma unroll
                for (int j = 0; j < TN; j++)
                    acc[i][j] = fmaf(a[i], b[j], acc[i][j]);
        }
        __syncthreads();
    }

#pragma unroll
    for (int i = 0; i < TM; i++) {
        int m = m0 + ty * TM + i;
        if (m >= M) continue;
#pragma unroll
        for (int j = 0; j < TN; j++) {
            int n = n0 + tx * TN + j;
            float v = acc[i][j] + bias[n];
            if (ADDD) v += D[(size_t)m * N + n];
            if (ELU_ACT) v = elu_f(v);
            C[(size_t)m * N + n] = v;
            if (STORE4) out4[(size_t)m * 256 + n * 4 + layer] = v;
        }
    }
}

// ---------------- small helper kernels ----------------
__global__ void zero_agg_k() {
    int i = blockIdx.x * 256 + threadIdx.x;
    if (i < N_NODES * 64) g_agg[i] = 0.f;
}

__global__ void msg_scatter_k(const float* __restrict__ x,
                              const int* __restrict__ ei)
{
    int e = blockIdx.x;
    int o = threadIdx.x;  // 64 threads
    __shared__ float xs[16];
    int s = ei[e];
    int d = ei[N_EDGES + e];
    if (s < 0 || s >= N_NODES || d < 0 || d >= N_NODES) return;
    if (o < 16) xs[o] = x[(size_t)s * 16 + o];
    __syncthreads();
    float acc = 0.f;
    const float* zr = g_big2 + (size_t)e * 1024;
#pragma unroll
    for (int i = 0; i < 16; i++)
        acc = fmaf(xs[i], zr[i * 64 + o], acc);
    atomicAdd(&g_agg[d * 64 + o], acc);
}

__global__ void elu_copy_k() {
    int i = blockIdx.x * 256 + threadIdx.x;
    if (i < N_NODES * 64) {
        float w = elu_f(g_xcur[i]);
        g_xin[i] = w;
        g_hbuf[i] = w;
    }
}

__global__ void gather_scatter_k(const int* __restrict__ ei) {
    int idx = blockIdx.x * 256 + threadIdx.x;
    if (idx >= N_EDGES * 64) return;
    int e = idx >> 6;
    int o = idx & 63;
    int s = ei[e];
    int d = ei[N_EDGES + e];
    if (s < 0 || s >= N_NODES || d < 0 || d >= N_NODES) return;
    atomicAdd(&g_hbuf[d * 64 + o], g_xin[s * 64 + o]);
}

// ---------------- launch ----------------
static inline int cdiv(int a, int b) { return (a + b - 1) / b; }

extern "C" void kernel_launch(void* const* d_in, const int* in_sizes, int n_in,
                              void* d_out, int out_size)
{
    const float* x   = (const float*)d_in[0];
    const int*   ei  = (const int*)d_in[1];
    const float* ea  = (const float*)d_in[2];
    const float* ew1 = (const float*)d_in[3];
    const float* eb1 = (const float*)d_in[4];
    const float* ew2 = (const float*)d_in[5];
    const float* eb2 = (const float*)d_in[6];
    const float* ew3 = (const float*)d_in[7];
    const float* eb3 = (const float*)d_in[8];
    const float* rw  = (const float*)d_in[9];
    const float* rb  = (const float*)d_in[10];
    const float* gw1 = (const float*)d_in[11];
    const float* gb1 = (const float*)d_in[12];
    const float* gw2 = (const float*)d_in[13];
    const float* gb2 = (const float*)d_in[14];
    const float* gw3 = (const float*)d_in[15];
    const float* gb3 = (const float*)d_in[16];
    float* out = (float*)d_out;

    // ---- Layer 0: NNConv (all f32x2 packed-FMA GEMMs) ----
    // h1 = elu(edge_attr @ enn_w1 + b1)   [200000,16]@[16,256]
    gemm2_k<<<dim3(2, cdiv(N_EDGES,128)), 256>>>(N_EDGES, 256, 16, ea, 0, ew1, eb1, 1);
    // h2 = elu(h1 @ enn_w2 + b2)          [200000,256]@[256,1024]
    gemm2_k<<<dim3(8, cdiv(N_EDGES,128)), 256>>>(N_EDGES, 1024, 256, nullptr, 1, ew2, eb2, 2);
    // z = elu(h2 @ enn_w3 + b3)           [200000,1024]@[1024,1024]
    gemm2_k<<<dim3(8, cdiv(N_EDGES,128)), 256>>>(N_EDGES, 1024, 1024, nullptr, 2, ew3, eb3, 3);

    // agg = segment_sum(einsum(x[src], w_e), dst)
    zero_agg_k<<<cdiv(N_NODES*64, 256), 256>>>();
    msg_scatter_k<<<N_EDGES, 64>>>(x, ei);

    // xcur = x @ root_w + agg + root_b ; store out[:,:,0]
    gemm_k<128,64,16,8,4, false,true,true>
        <<<dim3(1, cdiv(N_NODES,128)), 256>>>(N_NODES, 64, 16,
            x, 0, rw, rb, 4, 5, out, 0);

    // ---- Layers 1..3: GINConv ----
    for (int l = 0; l < 3; l++) {
        elu_copy_k<<<cdiv(N_NODES*64, 256), 256>>>();
        gather_scatter_k<<<cdiv(N_EDGES*64, 256), 256>>>(ei);
        // gh1 = elu(hbuf @ gin_w1[l] + gb1[l])   [50000,64]@[64,256]
        gemm2_k<<<dim3(2, cdiv(N_NODES,128)), 256>>>(N_NODES, 256, 64,
            nullptr, 7, gw1 + (size_t)l*64*256, gb1 + l*256, 8);
        // gh2 = elu(gh1 @ gin_w2[l] + gb2[l])    [50000,256]@[256,256]
        gemm2_k<<<dim3(2, cdiv(N_NODES,128)), 256>>>(N_NODES, 256, 256,
            nullptr, 8, gw2 + (size_t)l*256*256, gb2 + l*256, 9);
        // xcur = gh2 @ gin_w3[l] + gb3[l] ; store out[:,:,l+1]
        gemm_k<128,64,16,8,4, false,false,true>
            <<<dim3(1, cdiv(N_NODES,128)), 256>>>(N_NODES, 64, 256,
                nullptr, 9, gw3 + (size_t)l*256*64, gb3 + l*64, 0, 5, out, l + 1);
    }
}

// round 8
// speedup vs baseline: 5.3869x; 5.3869x over previous
#include <cuda_runtime.h>
#include <stdint.h>
#include <math.h>

#define N_NODES 50000
#define N_EDGES 200000

// ---------------- scratch (static __device__; no allocation allowed) ----------------
__device__ __align__(16) float g_h1 [(size_t)N_EDGES * 256];    // enn hidden 1 (row-major)
__device__ __align__(16) float g_big1[(size_t)N_EDGES * 1024];  // h2 (row-major)
__device__ __align__(16) float g_big2[(size_t)N_EDGES * 1024];  // z = elu(h2@w3+b3)
__device__ __align__(16) float g_agg [N_NODES * 64];
__device__ __align__(16) float g_xcur[N_NODES * 64];
__device__ __align__(16) float g_xin [N_NODES * 64];
__device__ __align__(16) float g_hbuf[N_NODES * 64];
__device__ __align__(16) float g_gh1 [N_NODES * 256];
__device__ __align__(16) float g_gh2 [N_NODES * 256];
// pre-packed, pre-rounded tf32 weights (frag-tile-major)
// ew2p @0 (64 tiles), ew3p @262144 (256 tiles), gw1p @1310720 (3x4 tiles), gw2p @1359872 (3x16 tiles)
#define BP_EW2 0
#define BP_EW3 262144
#define BP_GW1 1310720
#define BP_GW2 1359872
__device__ __align__(16) uint32_t g_bp[1556480];

__device__ __forceinline__ float* sbuf(int id) {
    switch (id) {
        case 1: return g_h1;
        case 2: return g_big1;
        case 3: return g_big2;
        case 4: return g_agg;
        case 5: return g_xcur;
        case 6: return g_xin;
        case 7: return g_hbuf;
        case 8: return g_gh1;
        case 9: return g_gh2;
    }
    return nullptr;
}

__device__ __forceinline__ float elu_f(float v) {
    return v > 0.f ? v : expm1f(v);
}
__device__ __forceinline__ uint32_t f2tf32(float f) {
    uint32_t u;
    asm("cvt.rna.tf32.f32 %0, %1;" : "=r"(u) : "f"(f));
    return u;
}

// ---- weight prepack: W[K,N] row-major fp32 -> frag-tile-major tf32 u32 ----
// tile (kt,nt) of 32x128; inner u32 idx = ((ks*16 + nf)*32 + t)*2 + v
//   k = kt*32 + ks*8 + (t&3) + v*4 ;  n = nt*128 + nf*8 + (t>>2)
__global__ void bprep_k(const float* __restrict__ W, int K, int N, int outOfs) {
    int o = blockIdx.x * 256 + threadIdx.x;
    int total = K * N;
    if (o >= total) return;
    int ntiles = N >> 7;
    int tile = o >> 12, inner = o & 4095;
    int kt = tile / ntiles, nt = tile % ntiles;
    int v = inner & 1, t = (inner >> 1) & 31, nf = (inner >> 6) & 15, ks = inner >> 10;
    int k = kt * 32 + ks * 8 + (t & 3) + v * 4;
    int n = nt * 128 + nf * 8 + (t >> 2);
    g_bp[outOfs + o] = f2tf32(W[(size_t)k * N + n]);
}

// =============== tf32 mma.sync GEMM v2: C = elu(A@B + bias) ===============
// A: scratch[Aid] [M,K] row-major fp32 (rounded at pack). B: g_bp+Bofs frag-tiles.
// CTA 128x128, BK=32, 128 threads = 4 warps of 64x64. grid (N/128, ceil(M/128)).
__global__ __launch_bounds__(128, 2)
void tmma_k(int M, int N, int K, int Aid, int Bofs,
            const float* __restrict__ bias, int Cid)
{
    const float* A = sbuf(Aid);
    float*       C = sbuf(Cid);

    // frag-major: sA[ks4][mf8][t32][v4], sB[ks4][nf16][t32][v2]
    __shared__ __align__(16) uint32_t sA[4096];
    __shared__ __align__(16) uint32_t sB[4096];

    const int tid  = threadIdx.x;
    const int lane = tid & 31;
    const int w    = tid >> 5;
    const int mw   = w >> 1;          // 0..1
    const int nw   = w & 1;           // 0..1
    const int m0 = blockIdx.y * 128;
    const int n0 = blockIdx.x * 128;
    const int nt = blockIdx.x;
    const int ntiles = N >> 7;

    float acc[4][8][4];
#pragma unroll
    for (int i = 0; i < 4; i++)
#pragma unroll
        for (int j = 0; j < 8; j++)
#pragma unroll
            for (int v = 0; v < 4; v++) acc[i][j][v] = 0.f;

    const int nslab = K >> 5;
    for (int sl = 0; sl < nslab; ++sl) {
        const int kk = sl << 5;
        __syncthreads();
        // ---- B: raw 16KB tile copy (pre-packed, pre-rounded) ----
        {
            const uint32_t* src = g_bp + Bofs + ((size_t)sl * ntiles + nt) * 4096;
#pragma unroll
            for (int i = 0; i < 8; ++i) {
                int o = i * 512 + tid * 4;
                *(uint4*)(sB + o) = *(const uint4*)(src + o);
            }
        }
        // ---- A: pack [128x32] row-major -> frag-major with cvt, STS.128 ----
#pragma unroll
        for (int it = 0; it < 8; ++it) {
            int u = it * 128 + tid;          // 0..1023
            int frag = u >> 5;               // (ks<<3)|mf8
            int t = u & 31;
            int mf8 = frag & 7, ks = frag >> 3;
            int r0 = m0 + mf8 * 16 + (t >> 2);
            int r1 = r0 + 8;
            int k0 = kk + ks * 8 + (t & 3);
            float v0 = 0.f, v1 = 0.f, v2 = 0.f, v3 = 0.f;
            if (r0 < M) { v0 = A[(size_t)r0 * K + k0]; v2 = A[(size_t)r0 * K + k0 + 4]; }
            if (r1 < M) { v1 = A[(size_t)r1 * K + k0]; v3 = A[(size_t)r1 * K + k0 + 4]; }
            uint4 wv = { f2tf32(v0), f2tf32(v1), f2tf32(v2), f2tf32(v3) };
            *(uint4*)(sA + u * 4) = wv;
        }
        __syncthreads();

        // ---- compute: 4 ksteps, warp tile 64x64 ----
#pragma unroll
        for (int ks = 0; ks < 4; ++ks) {
            uint32_t a[4][4];
#pragma unroll
            for (int mf = 0; mf < 4; ++mf) {
                int mf8 = mw * 4 + mf;
                uint4 t4 = *(const uint4*)(sA + (((ks << 3) + mf8) * 32 + lane) * 4);
                a[mf][0] = t4.x; a[mf][1] = t4.y; a[mf][2] = t4.z; a[mf][3] = t4.w;
            }
            uint32_t b[8][2];
#pragma unroll
            for (int nf_ = 0; nf_ < 8; ++nf_) {
                int nf = nw * 8 + nf_;
                uint2 t2 = *(const uint2*)(sB + (((ks << 4) + nf) * 32 + lane) * 2);
                b[nf_][0] = t2.x; b[nf_][1] = t2.y;
            }
#pragma unroll
            for (int mf = 0; mf < 4; ++mf)
#pragma unroll
                for (int nf_ = 0; nf_ < 8; ++nf_) {
                    asm volatile(
                        "mma.sync.aligned.m16n8k8.row.col.f32.tf32.tf32.f32 "
                        "{%0,%1,%2,%3}, {%4,%5,%6,%7}, {%8,%9}, {%0,%1,%2,%3};"
                        : "+f"(acc[mf][nf_][0]), "+f"(acc[mf][nf_][1]),
                          "+f"(acc[mf][nf_][2]), "+f"(acc[mf][nf_][3])
                        : "r"(a[mf][0]), "r"(a[mf][1]), "r"(a[mf][2]), "r"(a[mf][3]),
                          "r"(b[nf_][0]), "r"(b[nf_][1]));
                }
        }
    }

    // ---- epilogue: bias + ELU, float2 stores, row-major ----
    const int g  = lane >> 2;
    const int c2 = (lane & 3) << 1;
#pragma unroll
    for (int mf = 0; mf < 4; ++mf) {
        int r0 = m0 + mw * 64 + mf * 16 + g;
        int r1 = r0 + 8;
#pragma unroll
        for (int nf_ = 0; nf_ < 8; ++nf_) {
            int col = n0 + nw * 64 + nf_ * 8 + c2;
            float b0 = __ldg(bias + col), b1 = __ldg(bias + col + 1);
            if (r0 < M) {
                float2 o;
                o.x = elu_f(acc[mf][nf_][0] + b0);
                o.y = elu_f(acc[mf][nf_][1] + b1);
                *(float2*)(C + (size_t)r0 * N + col) = o;
            }
            if (r1 < M) {
                float2 o;
                o.x = elu_f(acc[mf][nf_][2] + b0);
                o.y = elu_f(acc[mf][nf_][3] + b1);
                *(float2*)(C + (size_t)r1 * N + col) = o;
            }
        }
    }
}

// ---------------- SIMT tiled GEMM (exact fp32) for small-N layers -----------------
template<int BM, int BN, int BK, int TM, int TN, bool ELU_ACT, bool ADDD, bool STORE4>
__global__ __launch_bounds__(256, 2)
void gemm_k(int M, int N, int K,
            const float* __restrict__ Aext, int Aid,
            const float* __restrict__ B,
            const float* __restrict__ bias,
            int Did, int Cid,
            float* __restrict__ out4, int layer)
{
    const float* A = (Aid == 0) ? Aext : sbuf(Aid);
    const float* D = ADDD ? sbuf(Did) : nullptr;
    float*       C = sbuf(Cid);

    __shared__ float As[BK][BM];
    __shared__ float Bs[BK][BN];

    const int tid = threadIdx.x;
    constexpr int TW = BN / TN;
    const int tx = tid % TW;
    const int ty = tid / TW;
    const int m0 = blockIdx.y * BM;
    const int n0 = blockIdx.x * BN;

    float acc[TM][TN];
#pragma unroll
    for (int i = 0; i < TM; i++)
#pragma unroll
        for (int j = 0; j < TN; j++) acc[i][j] = 0.f;

    constexpr int A_ITERS = (BM * BK) / (256 * 4);
    constexpr int B_ITERS = (BK * BN) / (256 * 4);

    for (int kk = 0; kk < K; kk += BK) {
#pragma unroll
        for (int it = 0; it < A_ITERS; ++it) {
            int i = tid * 4 + it * 1024;
            int r = i / BK;
            int c = i % BK;
            int m = m0 + r;
            float4 v;
            if (m < M) v = *(const float4*)(A + (size_t)m * K + kk + c);
            else       v = make_float4(0.f, 0.f, 0.f, 0.f);
            As[c + 0][r] = v.x;
            As[c + 1][r] = v.y;
            As[c + 2][r] = v.z;
            As[c + 3][r] = v.w;
        }
#pragma unroll
        for (int it = 0; it < B_ITERS; ++it) {
            int i = tid * 4 + it * 1024;
            int r = i / BN;
            int c = i % BN;
            *(float4*)(&Bs[r][c]) = *(const float4*)(B + (size_t)(kk + r) * N + n0 + c);
        }
        __syncthreads();

#pragma unroll
        for (int k = 0; k < BK; k++) {
            float a[TM], b[TN];
#pragma unroll
            for (int i = 0; i < TM; i += 4)
                *(float4*)&a[i] = *(const float4*)&As[k][ty * TM + i];
#pragma unroll
            for (int j = 0; j < TN; j += 4)
                *(float4*)&b[j] = *(const float4*)&Bs[k][tx * TN + j];
#pragma unroll
            for (int i = 0; i < TM; i++)
#pragma unroll
                for (int j = 0; j < TN; j++)
                    acc[i][j] = fmaf(a[i], b[j], acc[i][j]);
        }
        __syncthreads();
    }

#pragma unroll
    for (int i = 0; i < TM; i++) {
        int m = m0 + ty * TM + i;
        if (m >= M) continue;
#pragma unroll
        for (int j = 0; j < TN; j++) {
            int n = n0 + tx * TN + j;
            float v = acc[i][j] + bias[n];
            if (ADDD) v += D[(size_t)m * N + n];
            if (ELU_ACT) v = elu_f(v);
            C[(size_t)m * N + n] = v;
            if (STORE4) out4[(size_t)m * 256 + n * 4 + layer] = v;
        }
    }
}

// ---------------- small helper kernels ----------------
__global__ void zero_agg_k() {
    int i = blockIdx.x * 256 + threadIdx.x;
    if (i < N_NODES * 64) g_agg[i] = 0.f;
}

__global__ void msg_scatter_k(const float* __restrict__ x,
                              const int* __restrict__ ei)
{
    int e = blockIdx.x;
    int o = threadIdx.x;  // 64 threads
    __shared__ float xs[16];
    int s = ei[e];
    int d = ei[N_EDGES + e];
    if (s < 0 || s >= N_NODES || d < 0 || d >= N_NODES) return;
    if (o < 16) xs[o] = x[(size_t)s * 16 + o];
    __syncthreads();
    float acc = 0.f;
    const float* zr = g_big2 + (size_t)e * 1024;
#pragma unroll
    for (int i = 0; i < 16; i++)
        acc = fmaf(xs[i], zr[i * 64 + o], acc);
    atomicAdd(&g_agg[d * 64 + o], acc);
}

__global__ void elu_copy_k() {
    int i = blockIdx.x * 256 + threadIdx.x;
    if (i < N_NODES * 64) {
        float w = elu_f(g_xcur[i]);
        g_xin[i] = w;
        g_hbuf[i] = w;
    }
}

__global__ void gather_scatter_k(const int* __restrict__ ei) {
    int idx = blockIdx.x * 256 + threadIdx.x;
    if (idx >= N_EDGES * 64) return;
    int e = idx >> 6;
    int o = idx & 63;
    int s = ei[e];
    int d = ei[N_EDGES + e];
    if (s < 0 || s >= N_NODES || d < 0 || d >= N_NODES) return;
    atomicAdd(&g_hbuf[d * 64 + o], g_xin[s * 64 + o]);
}

// ---------------- launch ----------------
static inline int cdiv(int a, int b) { return (a + b - 1) / b; }

extern "C" void kernel_launch(void* const* d_in, const int* in_sizes, int n_in,
                              void* d_out, int out_size)
{
    const float* x   = (const float*)d_in[0];
    const int*   ei  = (const int*)d_in[1];
    const float* ea  = (const float*)d_in[2];
    const float* ew1 = (const float*)d_in[3];
    const float* eb1 = (const float*)d_in[4];
    const float* ew2 = (const float*)d_in[5];
    const float* eb2 = (const float*)d_in[6];
    const float* ew3 = (const float*)d_in[7];
    const float* eb3 = (const float*)d_in[8];
    const float* rw  = (const float*)d_in[9];
    const float* rb  = (const float*)d_in[10];
    const float* gw1 = (const float*)d_in[11];
    const float* gb1 = (const float*)d_in[12];
    const float* gw2 = (const float*)d_in[13];
    const float* gb2 = (const float*)d_in[14];
    const float* gw3 = (const float*)d_in[15];
    const float* gb3 = (const float*)d_in[16];
    float* out = (float*)d_out;

    // ---- pre-pack weights into frag-tile tf32 (cheap; once per replay) ----
    bprep_k<<<cdiv(256*1024, 256), 256>>>(ew2, 256, 1024, BP_EW2);
    bprep_k<<<cdiv(1024*1024, 256), 256>>>(ew3, 1024, 1024, BP_EW3);
    for (int l = 0; l < 3; l++) {
        bprep_k<<<cdiv(64*256, 256), 256>>>(gw1 + (size_t)l*64*256, 64, 256, BP_GW1 + l*16384);
        bprep_k<<<cdiv(256*256, 256), 256>>>(gw2 + (size_t)l*256*256, 256, 256, BP_GW2 + l*65536);
    }

    // ---- Layer 0: NNConv ----
    // h1 = elu(edge_attr @ enn_w1 + b1)   [200000,16]@[16,256]  (SIMT)
    gemm_k<128,128,16,8,8, true,false,false>
        <<<dim3(2, cdiv(N_EDGES,128)), 256>>>(N_EDGES, 256, 16,
            ea, 0, ew1, eb1, 0, 1, nullptr, 0);
    // h2 = elu(h1 @ enn_w2 + b2)          [200000,256]@[256,1024]  (tf32 mma v2)
    tmma_k<<<dim3(8, cdiv(N_EDGES,128)), 128>>>(N_EDGES, 1024, 256, 1, BP_EW2, eb2, 2);
    // z = elu(h2 @ enn_w3 + b3)           [200000,1024]@[1024,1024] (tf32 mma v2)
    tmma_k<<<dim3(8, cdiv(N_EDGES,128)), 128>>>(N_EDGES, 1024, 1024, 2, BP_EW3, eb3, 3);

    // agg = segment_sum(einsum(x[src], w_e), dst)
    zero_agg_k<<<cdiv(N_NODES*64, 256), 256>>>();
    msg_scatter_k<<<N_EDGES, 64>>>(x, ei);

    // xcur = x @ root_w + agg + root_b ; store out[:,:,0]
    gemm_k<128,64,16,8,4, false,true,true>
        <<<dim3(1, cdiv(N_NODES,128)), 256>>>(N_NODES, 64, 16,
            x, 0, rw, rb, 4, 5, out, 0);

    // ---- Layers 1..3: GINConv ----
    for (int l = 0; l < 3; l++) {
        elu_copy_k<<<cdiv(N_NODES*64, 256), 256>>>();
        gather_scatter_k<<<cdiv(N_EDGES*64, 256), 256>>>(ei);
        // gh1 = elu(hbuf @ gin_w1[l] + gb1[l])   [50000,64]@[64,256]  (mma v2)
        tmma_k<<<dim3(2, cdiv(N_NODES,128)), 128>>>(N_NODES, 256, 64, 7,
            BP_GW1 + l*16384, gb1 + l*256, 8);
        // gh2 = elu(gh1 @ gin_w2[l] + gb2[l])    [50000,256]@[256,256] (mma v2)
        tmma_k<<<dim3(2, cdiv(N_NODES,128)), 128>>>(N_NODES, 256, 256, 8,
            BP_GW2 + l*65536, gb2 + l*256, 9);
        // xcur = gh2 @ gin_w3[l] + gb3[l] ; store out[:,:,l+1]  (SIMT exact)
        gemm_k<128,64,16,8,4, false,false,true>
            <<<dim3(1, cdiv(N_NODES,128)), 256>>>(N_NODES, 64, 256,
                nullptr, 9, gw3 + (size_t)l*256*64, gb3 + l*64, 0, 5, out, l + 1);
    }
}

// round 9
// speedup vs baseline: 8.5007x; 1.5780x over previous
#include <cuda_runtime.h>
#include <stdint.h>
#include <math.h>

#define N_NODES 50000
#define N_EDGES 200000
#define MT_E 1563   // ceil(200000/128)
#define MT_N 391    // ceil(50000/128)

// ---------------- scratch (static __device__; no allocation allowed) ----------------
// frag-major tf32 activation buffers (u32)
__device__ __align__(16) uint32_t g_h1u [(size_t)MT_E * 8 * 4096];    // h1 packed (K=256)
__device__ __align__(16) uint32_t g_big1u[(size_t)MT_E * 32 * 4096];  // h2 packed (K=1024)
__device__ __align__(16) uint32_t g_gh1u [(size_t)MT_N * 8 * 4096];   // gh1 packed (K=256)
__device__ __align__(16) uint32_t g_hbfu [(size_t)MT_N * 2 * 4096];   // hbuf packed (K=64)
// fp32 row-major buffers
__device__ __align__(16) float g_big2[(size_t)N_EDGES * 1024];  // z = elu(h2@w3+b3)
__device__ __align__(16) float g_agg [N_NODES * 64];
__device__ __align__(16) float g_xcur[N_NODES * 64];
__device__ __align__(16) float g_xin [N_NODES * 64];
__device__ __align__(16) float g_hbuf[N_NODES * 64];
__device__ __align__(16) float g_gh2 [N_NODES * 256];
// pre-packed tf32 weights (frag-tile-major)
#define BP_EW2 0
#define BP_EW3 262144
#define BP_GW1 1310720
#define BP_GW2 1359872
__device__ __align__(16) uint32_t g_bp[1556480];

__device__ __forceinline__ float* sbuf(int id) {
    switch (id) {
        case 3: return g_big2;
        case 4: return g_agg;
        case 5: return g_xcur;
        case 6: return g_xin;
        case 7: return g_hbuf;
        case 9: return g_gh2;
    }
    return nullptr;
}
__device__ __forceinline__ uint32_t* ubuf(int id) {
    switch (id) {
        case 1:  return g_h1u;
        case 2:  return g_big1u;
        case 8:  return g_gh1u;
        case 10: return g_hbfu;
    }
    return nullptr;
}

__device__ __forceinline__ float elu_f(float v) {
    return v > 0.f ? v : expm1f(v);
}
__device__ __forceinline__ uint32_t f2tf32(float f) {
    uint32_t u;
    asm("cvt.rna.tf32.f32 %0, %1;" : "=r"(u) : "f"(f));
    return u;
}
__device__ __forceinline__ uint32_t smem_u32p(const void* p) {
    uint32_t a;
    asm("{ .reg .u64 t; cvta.to.shared.u64 t, %1; cvt.u32.u64 %0, t; }" : "=r"(a) : "l"(p));
    return a;
}
__device__ __forceinline__ void cpa16(uint32_t saddr, const void* g) {
    asm volatile("cp.async.cg.shared.global [%0], [%1], 16;" :: "r"(saddr), "l"(g) : "memory");
}

// A-frag offset for element (r,k) in an [M,K] operand (tiles 128x32):
__device__ __forceinline__ size_t afrag_off(int r, int k, int K) {
    return ((size_t)(r >> 7) * (K >> 5) + (k >> 5)) * 4096
         + ((((((k >> 3) & 3) << 3) | ((r >> 4) & 7)) * 32)
            + (((r & 7) << 2) | (k & 3))) * 4
         + (((r >> 3) & 1) | (((k >> 2) & 1) << 1));
}

// ---- weight prepack: W[K,N] row-major -> frag-tile tf32 (B operand) ----
__global__ void bprep_k(const float* __restrict__ W, int K, int N, int outOfs) {
    int o = blockIdx.x * 256 + threadIdx.x;
    if (o >= K * N) return;
    int ntiles = N >> 7;
    int tile = o >> 12, inner = o & 4095;
    int kt = tile / ntiles, nt = tile % ntiles;
    int v = inner & 1, t = (inner >> 1) & 31, nf = (inner >> 6) & 15, ks = inner >> 10;
    int k = kt * 32 + ks * 8 + (t & 3) + v * 4;
    int n = nt * 128 + nf * 8 + (t >> 2);
    g_bp[outOfs + o] = f2tf32(W[(size_t)k * N + n]);
}

// ---- activation prepack: fp32 row-major [M,K] -> A-frag tf32 ----
__global__ void apack_k(int Aid, int M, int K, int outId, int total) {
    int o = blockIdx.x * 256 + threadIdx.x;
    if (o >= total) return;
    const float* A = sbuf(Aid);
    int ktiles = K >> 5;
    int tile = o >> 12, inner = o & 4095;
    int kt = tile % ktiles, mt = tile / ktiles;
    int v = inner & 3, t = (inner >> 2) & 31, frag = inner >> 7;
    int mf8 = frag & 7, ks = frag >> 3;
    int r = mt * 128 + mf8 * 16 + ((v & 1) << 3) + (t >> 2);
    int k = kt * 32 + ks * 8 + ((v >> 1) << 2) + (t & 3);
    float val = (r < M) ? A[(size_t)r * K + k] : 0.f;
    ubuf(outId)[o] = f2tf32(val);
}

// =============== tf32 mma.sync GEMM v3: pipelined raw-copy operands ===============
// A: ubuf(Aid) frag-tiles; B: g_bp+Bofs frag-tiles. CTA 128x128, BK=32, 256 thr (8 warps,
// warp tile 32x64), cp.async double-buffered. FRAG_OUT: write elu(out) as A-frag tf32
// into ubuf(Cid); else fp32 row-major elu(out) into sbuf(Cid).
template<bool FRAG_OUT>
__global__ __launch_bounds__(256, 2)
void tmma3_k(int M, int N, int K, int Aid, int Bofs,
             const float* __restrict__ bias, int Cid)
{
    extern __shared__ __align__(16) uint32_t smem[];
    // u32 layout: A0 @0, A1 @4096, B0 @8192, B1 @12288
    const uint32_t* Au = ubuf(Aid);
    const uint32_t sbase = smem_u32p(smem);

    const int tid = threadIdx.x, lane = tid & 31, w = tid >> 5;
    const int mw = w >> 1, nw = w & 1;
    const int m0 = blockIdx.y * 128, n0 = blockIdx.x * 128;
    const int ktiles = K >> 5, ntiles = N >> 7;
    const size_t abase = (size_t)blockIdx.y * ktiles * 4096;

    float acc[2][8][4];
#pragma unroll
    for (int i = 0; i < 2; i++)
#pragma unroll
        for (int j = 0; j < 8; j++)
#pragma unroll
            for (int v = 0; v < 4; v++) acc[i][j][v] = 0.f;

    const int nslab = ktiles;

    auto issue = [&](int sl) {
        int b = sl & 1;
        const uint32_t* asrc = Au + abase + (size_t)sl * 4096 + tid * 4;
        const uint32_t* bsrc = g_bp + Bofs + ((size_t)sl * ntiles + blockIdx.x) * 4096 + tid * 4;
        uint32_t sa = sbase + b * 16384 + tid * 16;
        uint32_t sb = sbase + 32768 + b * 16384 + tid * 16;
#pragma unroll
        for (int i = 0; i < 4; ++i) {
            cpa16(sa + i * 4096, asrc + i * 1024);
            cpa16(sb + i * 4096, bsrc + i * 1024);
        }
        asm volatile("cp.async.commit_group;" ::: "memory");
    };

    issue(0);
    for (int sl = 0; sl < nslab; ++sl) {
        if (sl + 1 < nslab) {
            issue(sl + 1);
            asm volatile("cp.async.wait_group 1;" ::: "memory");
        } else {
            asm volatile("cp.async.wait_group 0;" ::: "memory");
        }
        __syncthreads();

        const int b = sl & 1;
        const uint32_t* sA = smem + b * 4096;
        const uint32_t* sB = smem + 8192 + b * 4096;
#pragma unroll
        for (int ks = 0; ks < 4; ++ks) {
            uint32_t a[2][4];
#pragma unroll
            for (int mf = 0; mf < 2; ++mf) {
                int mf8 = mw * 2 + mf;
                uint4 t4 = *(const uint4*)(sA + (((ks << 3) | mf8) * 32 + lane) * 4);
                a[mf][0] = t4.x; a[mf][1] = t4.y; a[mf][2] = t4.z; a[mf][3] = t4.w;
            }
            uint32_t bb[8][2];
#pragma unroll
            for (int nf_ = 0; nf_ < 8; ++nf_) {
                int nf = nw * 8 + nf_;
                uint2 t2 = *(const uint2*)(sB + (((ks << 4) | nf) * 32 + lane) * 2);
                bb[nf_][0] = t2.x; bb[nf_][1] = t2.y;
            }
#pragma unroll
            for (int mf = 0; mf < 2; ++mf)
#pragma unroll
                for (int nf_ = 0; nf_ < 8; ++nf_) {
                    asm volatile(
                        "mma.sync.aligned.m16n8k8.row.col.f32.tf32.tf32.f32 "
                        "{%0,%1,%2,%3}, {%4,%5,%6,%7}, {%8,%9}, {%0,%1,%2,%3};"
                        : "+f"(acc[mf][nf_][0]), "+f"(acc[mf][nf_][1]),
                          "+f"(acc[mf][nf_][2]), "+f"(acc[mf][nf_][3])
                        : "r"(a[mf][0]), "r"(a[mf][1]), "r"(a[mf][2]), "r"(a[mf][3]),
                          "r"(bb[nf_][0]), "r"(bb[nf_][1]));
                }
        }
        __syncthreads();
    }

    // ---- epilogue ----
    const int g  = lane >> 2;
    const int c2 = (lane & 3) << 1;
    float*    Cf = FRAG_OUT ? nullptr : sbuf(Cid);
    uint32_t* Cu = FRAG_OUT ? ubuf(Cid) : nullptr;
#pragma unroll
    for (int mf = 0; mf < 2; ++mf) {
        int r0 = m0 + mw * 32 + mf * 16 + g;
        int r1 = r0 + 8;
#pragma unroll
        for (int nf_ = 0; nf_ < 8; ++nf_) {
            int col = n0 + nw * 64 + nf_ * 8 + c2;
            float b0 = __ldg(bias + col), b1 = __ldg(bias + col + 1);
            float v00 = elu_f(acc[mf][nf_][0] + b0);
            float v01 = elu_f(acc[mf][nf_][1] + b1);
            float v10 = elu_f(acc[mf][nf_][2] + b0);
            float v11 = elu_f(acc[mf][nf_][3] + b1);
            if (FRAG_OUT) {
                if (r0 < M) {
                    Cu[afrag_off(r0, col,     N)] = f2tf32(v00);
                    Cu[afrag_off(r0, col + 1, N)] = f2tf32(v01);
                }
                if (r1 < M) {
                    Cu[afrag_off(r1, col,     N)] = f2tf32(v10);
                    Cu[afrag_off(r1, col + 1, N)] = f2tf32(v11);
                }
            } else {
                if (r0 < M) *(float2*)(Cf + (size_t)r0 * N + col) = make_float2(v00, v01);
                if (r1 < M) *(float2*)(Cf + (size_t)r1 * N + col) = make_float2(v10, v11);
            }
        }
    }
}

// ---------------- SIMT tiled GEMM (exact fp32) ----------------
// STOREFRAG: write elu(out) as A-frag tf32 into ubuf(Cid) (for h1 -> ew2 chain)
template<int BM, int BN, int BK, int TM, int TN, bool ELU_ACT, bool ADDD, bool STORE4, bool STOREFRAG>
__global__ __launch_bounds__(256, 2)
void gemm_k(int M, int N, int K,
            const float* __restrict__ Aext, int Aid,
            const float* __restrict__ B,
            const float* __restrict__ bias,
            int Did, int Cid,
            float* __restrict__ out4, int layer)
{
    const float* A = (Aid == 0) ? Aext : sbuf(Aid);
    const float* D = ADDD ? sbuf(Did) : nullptr;

    __shared__ float As[BK][BM];
    __shared__ float Bs[BK][BN];

    const int tid = threadIdx.x;
    constexpr int TW = BN / TN;
    const int tx = tid % TW;
    const int ty = tid / TW;
    const int m0 = blockIdx.y * BM;
    const int n0 = blockIdx.x * BN;

    float acc[TM][TN];
#pragma unroll
    for (int i = 0; i < TM; i++)
#pragma unroll
        for (int j = 0; j < TN; j++) acc[i][j] = 0.f;

    constexpr int A_ITERS = (BM * BK) / (256 * 4);
    constexpr int B_ITERS = (BK * BN) / (256 * 4);

    for (int kk = 0; kk < K; kk += BK) {
#pragma unroll
        for (int it = 0; it < A_ITERS; ++it) {
            int i = tid * 4 + it * 1024;
            int r = i / BK;
            int c = i % BK;
            int m = m0 + r;
            float4 v;
            if (m < M) v = *(const float4*)(A + (size_t)m * K + kk + c);
            else       v = make_float4(0.f, 0.f, 0.f, 0.f);
            As[c + 0][r] = v.x;
            As[c + 1][r] = v.y;
            As[c + 2][r] = v.z;
            As[c + 3][r] = v.w;
        }
#pragma unroll
        for (int it = 0; it < B_ITERS; ++it) {
            int i = tid * 4 + it * 1024;
            int r = i / BN;
            int c = i % BN;
            *(float4*)(&Bs[r][c]) = *(const float4*)(B + (size_t)(kk + r) * N + n0 + c);
        }
        __syncthreads();

#pragma unroll
        for (int k = 0; k < BK; k++) {
            float a[TM], b[TN];
#pragma unroll
            for (int i = 0; i < TM; i += 4)
                *(float4*)&a[i] = *(const float4*)&As[k][ty * TM + i];
#pragma unroll
            for (int j = 0; j < TN; j += 4)
                *(float4*)&b[j] = *(const float4*)&Bs[k][tx * TN + j];
#pragma unroll
            for (int i = 0; i < TM; i++)
#pragma unroll
                for (int j = 0; j < TN; j++)
                    acc[i][j] = fmaf(a[i], b[j], acc[i][j]);
        }
        __syncthreads();
    }

    float*    Cf = STOREFRAG ? nullptr : sbuf(Cid);
    uint32_t* Cu = STOREFRAG ? ubuf(Cid) : nullptr;
#pragma unroll
    for (int i = 0; i < TM; i++) {
        int m = m0 + ty * TM + i;
        if (m >= M) continue;
#pragma unroll
        for (int j = 0; j < TN; j++) {
            int n = n0 + tx * TN + j;
            float v = acc[i][j] + bias[n];
            if (ADDD) v += D[(size_t)m * N + n];
            if (ELU_ACT) v = elu_f(v);
            if (STOREFRAG) {
                Cu[afrag_off(m, n, N)] = f2tf32(v);
            } else {
                Cf[(size_t)m * N + n] = v;
                if (STORE4) out4[(size_t)m * 256 + n * 4 + layer] = v;
            }
        }
    }
}

// ---------------- small helper kernels ----------------
__global__ void zero_agg_k() {
    int i = blockIdx.x * 256 + threadIdx.x;
    if (i < N_NODES * 64) g_agg[i] = 0.f;
}

__global__ void msg_scatter_k(const float* __restrict__ x,
                              const int* __restrict__ ei)
{
    int e = blockIdx.x;
    int o = threadIdx.x;  // 64 threads
    __shared__ float xs[16];
    int s = ei[e];
    int d = ei[N_EDGES + e];
    if (s < 0 || s >= N_NODES || d < 0 || d >= N_NODES) return;
    if (o < 16) xs[o] = x[(size_t)s * 16 + o];
    __syncthreads();
    float acc = 0.f;
    const float* zr = g_big2 + (size_t)e * 1024;
#pragma unroll
    for (int i = 0; i < 16; i++)
        acc = fmaf(xs[i], zr[i * 64 + o], acc);
    atomicAdd(&g_agg[d * 64 + o], acc);
}

__global__ void elu_copy_k() {
    int i = blockIdx.x * 256 + threadIdx.x;
    if (i < N_NODES * 64) {
        float w = elu_f(g_xcur[i]);
        g_xin[i] = w;
        g_hbuf[i] = w;
    }
}

__global__ void gather_scatter_k(const int* __restrict__ ei) {
    int idx = blockIdx.x * 256 + threadIdx.x;
    if (idx >= N_EDGES * 64) return;
    int e = idx >> 6;
    int o = idx & 63;
    int s = ei[e];
    int d = ei[N_EDGES + e];
    if (s < 0 || s >= N_NODES || d < 0 || d >= N_NODES) return;
    atomicAdd(&g_hbuf[d * 64 + o], g_xin[s * 64 + o]);
}

// ---------------- launch ----------------
static inline int cdiv(int a, int b) { return (a + b - 1) / b; }

extern "C" void kernel_launch(void* const* d_in, const int* in_sizes, int n_in,
                              void* d_out, int out_size)
{
    const float* x   = (const float*)d_in[0];
    const int*   ei  = (const int*)d_in[1];
    const float* ea  = (const float*)d_in[2];
    const float* ew1 = (const float*)d_in[3];
    const float* eb1 = (const float*)d_in[4];
    const float* ew2 = (const float*)d_in[5];
    const float* eb2 = (const float*)d_in[6];
    const float* ew3 = (const float*)d_in[7];
    const float* eb3 = (const float*)d_in[8];
    const float* rw  = (const float*)d_in[9];
    const float* rb  = (const float*)d_in[10];
    const float* gw1 = (const float*)d_in[11];
    const float* gb1 = (const float*)d_in[12];
    const float* gw2 = (const float*)d_in[13];
    const float* gb2 = (const float*)d_in[14];
    const float* gw3 = (const float*)d_in[15];
    const float* gb3 = (const float*)d_in[16];
    float* out = (float*)d_out;

    cudaFuncSetAttribute(tmma3_k<true>,  cudaFuncAttributeMaxDynamicSharedMemorySize, 65536);
    cudaFuncSetAttribute(tmma3_k<false>, cudaFuncAttributeMaxDynamicSharedMemorySize, 65536);

    // ---- pre-pack weights (cheap) ----
    bprep_k<<<cdiv(256*1024, 256), 256>>>(ew2, 256, 1024, BP_EW2);
    bprep_k<<<cdiv(1024*1024, 256), 256>>>(ew3, 1024, 1024, BP_EW3);
    for (int l = 0; l < 3; l++) {
        bprep_k<<<cdiv(64*256, 256), 256>>>(gw1 + (size_t)l*64*256, 64, 256, BP_GW1 + l*16384);
        bprep_k<<<cdiv(256*256, 256), 256>>>(gw2 + (size_t)l*256*256, 256, 256, BP_GW2 + l*65536);
    }

    // ---- Layer 0: NNConv ----
    // h1 = elu(ea@ew1+b1) -> frag tf32 (A of ew2 GEMM)
    gemm_k<128,128,16,8,8, true,false,false,true>
        <<<dim3(2, MT_E), 256>>>(N_EDGES, 256, 16, ea, 0, ew1, eb1, 0, 1, nullptr, 0);
    // h2 = elu(h1@ew2+b2) -> frag tf32 (A of ew3 GEMM)
    tmma3_k<true><<<dim3(8, MT_E), 256, 65536>>>(N_EDGES, 1024, 256, 1, BP_EW2, eb2, 2);
    // z = elu(h2@ew3+b3) -> row-major fp32 (consumed by msg_scatter)
    tmma3_k<false><<<dim3(8, MT_E), 256, 65536>>>(N_EDGES, 1024, 1024, 2, BP_EW3, eb3, 3);

    // agg = segment_sum(einsum(x[src], w_e), dst)
    zero_agg_k<<<cdiv(N_NODES*64, 256), 256>>>();
    msg_scatter_k<<<N_EDGES, 64>>>(x, ei);

    // xcur = x @ root_w + agg + root_b ; store out[:,:,0]
    gemm_k<128,64,16,8,4, false,true,true,false>
        <<<dim3(1, MT_N), 256>>>(N_NODES, 64, 16, x, 0, rw, rb, 4, 5, out, 0);

    // ---- Layers 1..3: GINConv ----
    const int hb_total = MT_N * 2 * 4096;
    for (int l = 0; l < 3; l++) {
        elu_copy_k<<<cdiv(N_NODES*64, 256), 256>>>();
        gather_scatter_k<<<cdiv(N_EDGES*64, 256), 256>>>(ei);
        // pack hbuf -> frag tf32
        apack_k<<<cdiv(hb_total, 256), 256>>>(7, N_NODES, 64, 10, hb_total);
        // gh1 = elu(hbuf@gw1+gb1) -> frag tf32
        tmma3_k<true><<<dim3(2, MT_N), 256, 65536>>>(N_NODES, 256, 64, 10,
            BP_GW1 + l*16384, gb1 + l*256, 8);
        // gh2 = elu(gh1@gw2+gb2) -> row-major fp32
        tmma3_k<false><<<dim3(2, MT_N), 256, 65536>>>(N_NODES, 256, 256, 8,
            BP_GW2 + l*65536, gb2 + l*256, 9);
        // xcur = gh2@gw3+gb3 ; store out[:,:,l+1]  (SIMT exact)
        gemm_k<128,64,16,8,4, false,false,true,false>
            <<<dim3(1, MT_N), 256>>>(N_NODES, 64, 256, nullptr, 9,
                gw3 + (size_t)l*256*64, gb3 + l*64, 0, 5, out, l + 1);
    }
}